// round 3
// baseline (speedup 1.0000x reference)
#include <cuda_runtime.h>
#include <cuda_bf16.h>
#include <math.h>
#include <stdint.h>

// ---------------- problem constants ----------------
#define VV    50000
#define OOV_N 100
#define VO    50100
#define EE    128
#define HH    256
#define BB    32
#define SS    256
#define TT    16
#define BTVO  ((size_t)BB * TT * VO)   // 25,651,200

// ---------------- static device scratch (no runtime alloc) ----------------
__device__ float d_xe_enc[BB * SS * EE];
__device__ float d_xe_dec[BB * TT * EE];
__device__ float d_zx_enc[(size_t)BB * SS * 4 * HH];
__device__ float d_zx_dec[BB * TT * 4 * HH];
__device__ float d_enc_out[(size_t)BB * SS * HH];
__device__ float d_dec_out[BB * TT * HH];
__device__ float d_ehec[2 * BB * HH];      // rows 0..31 = eh, 32..63 = ec
__device__ float d_h0c0[2 * BB * HH];      // rows 0..31 = h0, 32..63 = c0
__device__ float d_dWa[BB * TT * HH];
__device__ float d_encWc[(size_t)BB * SS * HH];
__device__ float d_cat[BB * TT * 2 * HH];
__device__ float d_attn[BB * TT * HH];
__device__ float d_rowsum[BB * TT];
__device__ float d_zero[BB * HH];          // stays zero forever

// grid-barrier state (self-resetting, safe across graph replays)
__device__ volatile unsigned g_bar_cnt;
__device__ volatile unsigned g_bar_gen;

// ================= grid barrier (all CTAs co-resident) =================
__device__ __forceinline__ void grid_barrier(unsigned nblocks) {
    __threadfence();
    __syncthreads();
    if (threadIdx.x == 0) {
        unsigned gen = g_bar_gen;
        unsigned arr = atomicAdd((unsigned*)&g_bar_cnt, 1u);
        if (arr == nblocks - 1u) {
            g_bar_cnt = 0u;
            __threadfence();
            g_bar_gen = gen + 1u;
        } else {
            while (g_bar_gen == gen) { }
        }
        __threadfence();
    }
    __syncthreads();
}

// ================= embedding gather (enc + dec) =================
__global__ void embed_kernel(const int* __restrict__ x, const int* __restrict__ dx,
                             const float* __restrict__ emb) {
    const int BSE = BB * SS * EE;
    const int BTE = BB * TT * EE;
    int g = blockIdx.x * blockDim.x + threadIdx.x;
    if (g < BSE) {
        int tok = x[g / EE];
        d_xe_enc[g] = emb[(size_t)tok * EE + (g % EE)];
    } else if (g < BSE + BTE) {
        int g2 = g - BSE;
        int tok = dx[g2 / EE];
        d_xe_dec[g2] = emb[(size_t)tok * EE + (g2 % EE)];
    }
}

// ================= generic SGEMM: C = op(A @ B + bias) =================
// A: MxK row-major, B: KxN row-major, C: MxN with row stride ldc.
// MODE 0: none, 1: tanh, 2: exp. K must be a multiple of 8 (true for 128/256/512).
template <int MODE>
__global__ void __launch_bounds__(256, 2)
sgemm_kernel(const float* __restrict__ A, const float* __restrict__ B,
             float* __restrict__ C, int M, int N, int K, int ldc,
             const float* __restrict__ bias) {
    __shared__ float As[8][132];
    __shared__ float Bs[8][132];

    const int tid  = threadIdx.x;
    const int row0 = blockIdx.y * 128;
    const int col0 = blockIdx.x * 128;
    const int rowb = (tid >> 4) * 8;
    const int colb = (tid & 15) * 8;

    float acc[8][8];
#pragma unroll
    for (int i = 0; i < 8; i++)
#pragma unroll
        for (int j = 0; j < 8; j++) acc[i][j] = 0.f;

    const int am  = tid >> 1;          // 0..127
    const int akq = (tid & 1) * 4;     // 0 or 4
    const int bkk = tid >> 5;          // 0..7
    const int bn4 = (tid & 31) * 4;    // 0..124

    for (int k0 = 0; k0 < K; k0 += 8) {
        // A tile -> As[k][m] (transposed)
        {
            float4 av = make_float4(0.f, 0.f, 0.f, 0.f);
            int r = row0 + am;
            if (r < M) av = *reinterpret_cast<const float4*>(&A[(size_t)r * K + k0 + akq]);
            As[akq + 0][am] = av.x;
            As[akq + 1][am] = av.y;
            As[akq + 2][am] = av.z;
            As[akq + 3][am] = av.w;
        }
        // B tile -> Bs[k][n]
        {
            int c = col0 + bn4;
            const float* brow = &B[(size_t)(k0 + bkk) * N];
            if (c + 3 < N) {
                *reinterpret_cast<float4*>(&Bs[bkk][bn4]) =
                    *reinterpret_cast<const float4*>(&brow[c]);
            } else {
#pragma unroll
                for (int j = 0; j < 4; j++)
                    Bs[bkk][bn4 + j] = (c + j < N) ? brow[c + j] : 0.f;
            }
        }
        __syncthreads();

#pragma unroll
        for (int kk = 0; kk < 8; kk++) {
            float a[8], b[8];
            float4 a0 = *reinterpret_cast<const float4*>(&As[kk][rowb]);
            float4 a1 = *reinterpret_cast<const float4*>(&As[kk][rowb + 4]);
            float4 b0 = *reinterpret_cast<const float4*>(&Bs[kk][colb]);
            float4 b1 = *reinterpret_cast<const float4*>(&Bs[kk][colb + 4]);
            a[0]=a0.x; a[1]=a0.y; a[2]=a0.z; a[3]=a0.w;
            a[4]=a1.x; a[5]=a1.y; a[6]=a1.z; a[7]=a1.w;
            b[0]=b0.x; b[1]=b0.y; b[2]=b0.z; b[3]=b0.w;
            b[4]=b1.x; b[5]=b1.y; b[6]=b1.z; b[7]=b1.w;
#pragma unroll
            for (int i = 0; i < 8; i++)
#pragma unroll
                for (int j = 0; j < 8; j++) acc[i][j] += a[i] * b[j];
        }
        __syncthreads();
    }

#pragma unroll
    for (int i = 0; i < 8; i++) {
        int r = row0 + rowb + i;
        if (r >= M) break;
#pragma unroll
        for (int j = 0; j < 8; j++) {
            int c = col0 + colb + j;
            if (c < N) {
                float v = acc[i][j];
                if (bias) v += bias[c];
                if (MODE == 1) v = tanhf(v);
                if (MODE == 2) v = expf(v);
                C[(size_t)r * ldc + c] = v;
            }
        }
    }
}

// ================= persistent LSTM =================
// 64 CTAs x 256 threads. CTA owns 4 hidden units (all 4 gates, all 32 batches).
// zx: [b][step][4H] precomputed x@W + bias. U: [K=256][4H]. hist: [b][step][H].
__global__ void __launch_bounds__(256, 1)
lstm_kernel(const float* __restrict__ zx, const float* __restrict__ U,
            const float* __restrict__ h0, const float* __restrict__ c0,
            float* __restrict__ hist, float* __restrict__ h_fin,
            float* __restrict__ c_fin, int steps) {
    __shared__ float hs[256 * 33];   // [k][b] padded
    __shared__ float zs[4 * 128];    // [gate][u*32+b]

    const int tid = threadIdx.x;
    const int u0  = blockIdx.x * 4;

    // gate-compute role
    const int bl = tid & 15;
    const int gg = (tid >> 4) & 3;
    const int uu_g = tid >> 6;
    const int j  = gg * 256 + u0 + uu_g;
    const int b1 = bl, b2 = bl + 16;

    // update role (tid < 128)
    const int ub = tid & 31;
    const int uu = tid >> 5;
    float c_reg = 0.f;
    if (tid < 128) c_reg = c0 ? c0[ub * 256 + u0 + uu] : 0.f;

    const unsigned nblk = gridDim.x;

    for (int s = 0; s < steps; s++) {
        // stage h_prev (32x256) into shared, transposed [k][b]
        if (s == 0) {
            for (int b = 0; b < 32; b++)
                hs[tid * 33 + b] = h0[b * 256 + tid];
        } else {
            for (int b = 0; b < 32; b++)
                hs[tid * 33 + b] = hist[((size_t)b * steps + (s - 1)) * 256 + tid];
        }
        __syncthreads();

        float a1 = zx[((size_t)b1 * steps + s) * 1024 + j];
        float a2 = zx[((size_t)b2 * steps + s) * 1024 + j];
#pragma unroll 8
        for (int k = 0; k < 256; k++) {
            float uk = U[k * 1024 + j];
            a1 += uk * hs[k * 33 + b1];
            a2 += uk * hs[k * 33 + b2];
        }
        zs[gg * 128 + uu_g * 32 + b1] = a1;
        zs[gg * 128 + uu_g * 32 + b2] = a2;
        __syncthreads();

        if (tid < 128) {
            float iv = zs[0 * 128 + uu * 32 + ub];
            float fv = zs[1 * 128 + uu * 32 + ub];
            float gv = zs[2 * 128 + uu * 32 + ub];
            float ov = zs[3 * 128 + uu * 32 + ub];
            float ig = 1.f / (1.f + expf(-iv));
            float fg = 1.f / (1.f + expf(-fv));
            float og = 1.f / (1.f + expf(-ov));
            c_reg = fg * c_reg + ig * tanhf(gv);
            float h = og * tanhf(c_reg);
            hist[((size_t)ub * steps + s) * 256 + u0 + uu] = h;
            if (s == steps - 1) {
                h_fin[ub * 256 + u0 + uu] = h;
                c_fin[ub * 256 + u0 + uu] = c_reg;
            }
        }
        grid_barrier(nblk);
    }
}

// ================= fused attention per (b,t) =================
// scores -> mask -> softmax -> ctx; writes cat = [ctx, dec_out]
__global__ void __launch_bounds__(256)
attn_kernel(const float* __restrict__ dWa, const float* __restrict__ enc,
            const float* __restrict__ dec, const int* __restrict__ x_len,
            float* __restrict__ cat) {
    __shared__ float q[256];
    __shared__ float aw[256];
    __shared__ float red[8];

    const int bt = blockIdx.x;
    const int b  = bt / TT;
    const int tid = threadIdx.x;

    q[tid] = dWa[(size_t)bt * 256 + tid];
    __syncthreads();

    // score for source position s = tid
    const float* er = enc + ((size_t)b * SS + tid) * 256;
    float dot = 0.f;
#pragma unroll 4
    for (int k = 0; k < 256; k += 4) {
        float4 e = *reinterpret_cast<const float4*>(&er[k]);
        dot += q[k] * e.x + q[k + 1] * e.y + q[k + 2] * e.z + q[k + 3] * e.w;
    }
    const int len = x_len[b];
    float sc = (tid < len) ? dot : -1e30f;

    // block max
    float m = sc;
#pragma unroll
    for (int o = 16; o; o >>= 1) m = fmaxf(m, __shfl_xor_sync(~0u, m, o));
    if ((tid & 31) == 0) red[tid >> 5] = m;
    __syncthreads();
    float mx = red[0];
#pragma unroll
    for (int w = 1; w < 8; w++) mx = fmaxf(mx, red[w]);
    __syncthreads();

    float e = (tid < len) ? expf(sc - mx) : 0.f;
    float sm = e;
#pragma unroll
    for (int o = 16; o; o >>= 1) sm += __shfl_xor_sync(~0u, sm, o);
    if ((tid & 31) == 0) red[tid >> 5] = sm;
    __syncthreads();
    float tot = 0.f;
#pragma unroll
    for (int w = 0; w < 8; w++) tot += red[w];
    aw[tid] = e / tot;
    __syncthreads();

    // ctx over s, thread = embedding dim
    float cx = 0.f;
    const float* eb = enc + (size_t)b * SS * 256 + tid;
    for (int s = 0; s < SS; s++) cx += aw[s] * eb[(size_t)s * 256];

    cat[(size_t)bt * 512 + tid]       = cx;
    cat[(size_t)bt * 512 + 256 + tid] = dec[(size_t)bt * 256 + tid];
}

// ================= pad OOV columns with 1e-10 =================
__global__ void pad_kernel(float* __restrict__ out) {
    int g = blockIdx.x * blockDim.x + threadIdx.x;
    if (g < BB * TT * OOV_N) {
        int row = g / OOV_N;
        out[(size_t)row * VO + VV + (g % OOV_N)] = 1e-10f;
    }
}

// ================= copy scores + scatter =================
__global__ void __launch_bounds__(256)
copy_scatter_kernel(const float* __restrict__ encWc, const float* __restrict__ attn,
                    const int* __restrict__ xov, const int* __restrict__ x_len,
                    float* __restrict__ out) {
    __shared__ float a[256];
    const int bt = blockIdx.x;
    const int b  = bt / TT;
    const int tid = threadIdx.x;

    a[tid] = attn[(size_t)bt * 256 + tid];
    __syncthreads();

    if (tid < x_len[b]) {
        const float* r = encWc + ((size_t)b * SS + tid) * 256;
        float dot = 0.f;
#pragma unroll 4
        for (int k = 0; k < 256; k += 4) {
            float4 e = *reinterpret_cast<const float4*>(&r[k]);
            dot += a[k] * e.x + a[k + 1] * e.y + a[k + 2] * e.z + a[k + 3] * e.w;
        }
        float v = expf(dot);
        atomicAdd(&out[(size_t)bt * VO + xov[b * SS + tid]], v);
    }
}

// ================= row sums =================
__global__ void __launch_bounds__(256)
rowsum_kernel(const float* __restrict__ out, float* __restrict__ rs) {
    __shared__ float red[8];
    const int row = blockIdx.x;
    const int tid = threadIdx.x;
    const float* r = out + (size_t)row * VO;
    float s = 0.f;
    for (int i = tid; i < VO; i += 256) s += r[i];
#pragma unroll
    for (int o = 16; o; o >>= 1) s += __shfl_xor_sync(~0u, s, o);
    if ((tid & 31) == 0) red[tid >> 5] = s;
    __syncthreads();
    if (tid == 0) {
        float t = 0.f;
#pragma unroll
        for (int w = 0; w < 8; w++) t += red[w];
        rs[row] = t;
    }
}

// ================= in-place log normalize =================
__global__ void lognorm_kernel(float* __restrict__ out, const float* __restrict__ rs) {
    size_t g = (size_t)blockIdx.x * blockDim.x + threadIdx.x;
    if (g < BTVO) {
        int row = (int)(g / VO);
        out[g] = logf(out[g]) - logf(rs[row]);
    }
}

// ================= host side =================
template <typename T>
static T* sym_addr(T& symbol) {
    void* p = nullptr;
    cudaGetSymbolAddress(&p, symbol);
    return (T*)p;
}

static void run_gemm(const float* A, const float* B, float* C, int M, int N, int K,
                     int ldc, const float* bias, int mode) {
    dim3 grid((N + 127) / 128, (M + 127) / 128);
    if (mode == 0)      sgemm_kernel<0><<<grid, 256>>>(A, B, C, M, N, K, ldc, bias);
    else if (mode == 1) sgemm_kernel<1><<<grid, 256>>>(A, B, C, M, N, K, ldc, bias);
    else                sgemm_kernel<2><<<grid, 256>>>(A, B, C, M, N, K, ldc, bias);
}

extern "C" void kernel_launch(void* const* d_in, const int* in_sizes, int n_in,
                              void* d_out, int out_size) {
    const int*   x     = (const int*)d_in[0];
    const int*   xov   = (const int*)d_in[1];
    const int*   xlen  = (const int*)d_in[2];
    const int*   dx    = (const int*)d_in[3];
    const float* emb   = (const float*)d_in[4];
    const float* Wenc  = (const float*)d_in[5];
    const float* Uenc  = (const float*)d_in[6];
    const float* benc  = (const float*)d_in[7];
    const float* We2d  = (const float*)d_in[8];
    const float* be2d  = (const float*)d_in[9];
    const float* Wdec  = (const float*)d_in[10];
    const float* Udec  = (const float*)d_in[11];
    const float* bdec  = (const float*)d_in[12];
    const float* Wattn = (const float*)d_in[13];
    const float* Wout  = (const float*)d_in[14];
    const float* bout  = (const float*)d_in[15];
    const float* Wgen  = (const float*)d_in[16];
    const float* Wcopy = (const float*)d_in[17];
    const float* bcopy = (const float*)d_in[18];
    float* out = (float*)d_out;

    float* xe_enc  = sym_addr(d_xe_enc[0])  ? (float*)nullptr : nullptr; // placeholder (unused)
    // Resolve scratch symbol addresses (host API, not captured as graph nodes)
    void* p;
    cudaGetSymbolAddress(&p, d_xe_enc);  float* s_xe_enc  = (float*)p;
    cudaGetSymbolAddress(&p, d_xe_dec);  float* s_xe_dec  = (float*)p;
    cudaGetSymbolAddress(&p, d_zx_enc);  float* s_zx_enc  = (float*)p;
    cudaGetSymbolAddress(&p, d_zx_dec);  float* s_zx_dec  = (float*)p;
    cudaGetSymbolAddress(&p, d_enc_out); float* s_enc_out = (float*)p;
    cudaGetSymbolAddress(&p, d_dec_out); float* s_dec_out = (float*)p;
    cudaGetSymbolAddress(&p, d_ehec);    float* s_ehec    = (float*)p;
    cudaGetSymbolAddress(&p, d_h0c0);    float* s_h0c0    = (float*)p;
    cudaGetSymbolAddress(&p, d_dWa);     float* s_dWa     = (float*)p;
    cudaGetSymbolAddress(&p, d_encWc);   float* s_encWc   = (float*)p;
    cudaGetSymbolAddress(&p, d_cat);     float* s_cat     = (float*)p;
    cudaGetSymbolAddress(&p, d_attn);    float* s_attn    = (float*)p;
    cudaGetSymbolAddress(&p, d_rowsum);  float* s_rowsum  = (float*)p;
    cudaGetSymbolAddress(&p, d_zero);    float* s_zero    = (float*)p;
    (void)xe_enc; (void)in_sizes; (void)n_in; (void)out_size;

    // 1. embeddings
    {
        int total = BB * SS * EE + BB * TT * EE;
        embed_kernel<<<(total + 255) / 256, 256>>>(x, dx, emb);
    }
    // 2/3. zx precompute (x@W + b)
    run_gemm(s_xe_enc, Wenc, s_zx_enc, BB * SS, 4 * HH, EE, 4 * HH, benc, 0);
    run_gemm(s_xe_dec, Wdec, s_zx_dec, BB * TT, 4 * HH, EE, 4 * HH, bdec, 0);
    // 4. encoder LSTM
    lstm_kernel<<<64, 256>>>(s_zx_enc, Uenc, s_zero, nullptr,
                             s_enc_out, s_ehec, s_ehec + BB * HH, SS);
    // 5. h0/c0 = [eh;ec] @ We2d + be2d
    run_gemm(s_ehec, We2d, s_h0c0, 2 * BB, HH, HH, HH, be2d, 0);
    // 6. decoder LSTM (final h,c straight into output tail)
    lstm_kernel<<<64, 256>>>(s_zx_dec, Udec, s_h0c0, s_h0c0 + BB * HH,
                             s_dec_out, out + BTVO, out + BTVO + BB * HH, TT);
    // 7. dWa = dec_out @ Wattn
    run_gemm(s_dec_out, Wattn, s_dWa, BB * TT, HH, HH, HH, nullptr, 0);
    // 8. encWc = tanh(enc_out @ Wcopy + bcopy)
    run_gemm(s_enc_out, Wcopy, s_encWc, BB * SS, HH, HH, HH, bcopy, 1);
    // 9. attention -> cat
    attn_kernel<<<BB * TT, 256>>>(s_dWa, s_enc_out, s_dec_out, xlen, s_cat);
    // 10. attn_out = tanh(cat @ Wout + bout)
    run_gemm(s_cat, Wout, s_attn, BB * TT, HH, 2 * HH, HH, bout, 1);
    // 11. gen = exp(attn_out @ Wgen) directly into out (row stride VO)
    run_gemm(s_attn, Wgen, out, BB * TT, VV, HH, VO, nullptr, 2);
    // 12. pad OOV region
    pad_kernel<<<(BB * TT * OOV_N + 255) / 256, 256>>>(out);
    // 13. copy scores + scatter
    copy_scatter_kernel<<<BB * TT, 256>>>(s_encWc, s_attn, xov, xlen, out);
    // 14. row sums
    rowsum_kernel<<<BB * TT, 256>>>(out, s_rowsum);
    // 15. log normalize in place
    {
        size_t total = BTVO;
        int blocks = (int)((total + 255) / 256);
        lognorm_kernel<<<blocks, 256>>>(out, s_rowsum);
    }
}